// round 8
// baseline (speedup 1.0000x reference)
#include <cuda_runtime.h>

#define NB 4
#define NA 160000
#define NG 64
#define NBLK 105             // K1 blocks per batch image (grid 105*4 = 420 <= 444 @occ3)
#define K1_STRIDE (NBLK*256) // 26880
#define NBLK6 100            // blocks 0..99: 6 anchors/thread; 100..104: 5 (100*6+5*5=625)

// Scratch (__device__ globals; no init required by construction)
__device__ uint2         g_best[NB * NA];            // (bits of best IoU, argmax gt)
__device__ float         g_blockmax[NB * NBLK * NG]; // per-block per-gt rounded col max
__device__ unsigned char g_lowq[NB * NA];            // low-quality flags (zeroed by K1)

// Same _rn sequence everywhere + __fdividef everywhere => any (anchor,gt) IoU
// is bit-identical between K1 and K2, so K2's rounded-equality rescan matches
// the reference's  mq == highest_per_gt  exactly.
__device__ __forceinline__ float box_area(float4 b) {
    return __fmul_rn(__fadd_rn(b.z, -b.x), __fadd_rn(b.w, -b.y));
}

__device__ __forceinline__ float iou_pair(float4 a, float areaA, float4 g, float areaG) {
    float ltx = fmaxf(g.x, a.x);
    float lty = fmaxf(g.y, a.y);
    float rbx = fminf(g.z, a.z);
    float rby = fminf(g.w, a.w);
    float w = fmaxf(__fadd_rn(rbx, -ltx), 0.0f);
    float h = fmaxf(__fadd_rn(rby, -lty), 0.0f);
    float inter = __fmul_rn(w, h);
    float denom = __fadd_rn(__fadd_rn(areaA, areaG), -inter);
    return __fdividef(inter, denom);   // RCP+FMUL; inter==0 -> exactly 0; denom>0 always
}

// ---------------------------------------------------------------------------
// K1: single full IoU pass on direct rounded quotients (reference semantics).
// Per thread: KA anchors in registers. Produces per-anchor (best, bestg),
// per-block per-gt rounded column max, zeroed lowq flags.
// ---------------------------------------------------------------------------
template <int KA>
__device__ __forceinline__ void k1_body(
    const float4* __restrict__ anchors, int b, int blk, int tid,
    const float4* sg, const float* sga, unsigned int* smax)
{
    const int a0 = blk * 256 + tid;
    const int lane = tid & 31;

    float4 an[KA]; float areaA[KA]; float best[KA]; int bg[KA];
#pragma unroll
    for (int k = 0; k < KA; ++k) {
        int a = a0 + k * K1_STRIDE;
        an[k] = anchors[b * NA + a];
        areaA[k] = box_area(an[k]);
        best[k] = -1.0f;               // first g always wins -> first-occurrence argmax
        bg[k] = 0;
        g_lowq[b * NA + a] = 0;        // each anchor touched exactly once
    }

    float gown[2] = {0.0f, 0.0f};      // rounded tile col-max for g = lane, lane+32

#pragma unroll 2
    for (int g = 0; g < NG; ++g) {
        float4 gb = sg[g];
        float  ag = sga[g];

        float cmax = 0.0f;             // this thread's column-max candidate
#pragma unroll
        for (int k = 0; k < KA; ++k) {
            float q = iou_pair(an[k], areaA[k], gb, ag);
            cmax = fmaxf(cmax, q);
            if (q > best[k]) { best[k] = q; bg[k] = g; }   // strict >: first occurrence
        }

        // warp-reduce the rounded column max
#pragma unroll
        for (int off = 16; off; off >>= 1)
            cmax = fmaxf(cmax, __shfl_xor_sync(0xffffffffu, cmax, off));
        if (lane == (g & 31))
            gown[g >> 5] = cmax;
    }

#pragma unroll
    for (int k = 0; k < KA; ++k) {
        int a = a0 + k * K1_STRIDE;
        g_best[b * NA + a] = make_uint2(__float_as_uint(best[k]), (unsigned)bg[k]);
    }

    // block-level rounded col-max (IoU >= 0: uint order == float order)
    atomicMax(&smax[lane],      __float_as_uint(gown[0]));
    atomicMax(&smax[lane + 32], __float_as_uint(gown[1]));
}

__global__ __launch_bounds__(256, 3)
void k_main(const float4* __restrict__ anchors, const float4* __restrict__ gts)
{
    const int b = blockIdx.y;
    const int blk = blockIdx.x;
    const int tid = threadIdx.x;

    __shared__ float4 sg[NG];
    __shared__ float  sga[NG];
    __shared__ unsigned int smax[NG];

    if (tid < NG) {
        float4 g = gts[b * NG + tid];
        sg[tid] = g;
        sga[tid] = box_area(g);
        smax[tid] = 0u;
    }
    __syncthreads();

    if (blk < NBLK6) k1_body<6>(anchors, b, blk, tid, sg, sga, smax);
    else             k1_body<5>(anchors, b, blk, tid, sg, sga, smax);

    __syncthreads();
    if (tid < NG)
        g_blockmax[(b * NBLK + blk) * NG + tid] = __uint_as_float(smax[tid]);
}

// ---------------------------------------------------------------------------
// K2: sparse low-quality pass. One block per (gt,batch) column: reduce the 105
// block maxima to the global column max, rescan only blocks achieving it, flag
// anchors whose rounded IoU equals it (exact reference semantics).
// ---------------------------------------------------------------------------
__global__ __launch_bounds__(256)
void k_lowq(const float4* __restrict__ anchors, const float4* __restrict__ gts)
{
    const int g = blockIdx.x;
    const int b = blockIdx.y;
    const int tid = threadIdx.x;

    __shared__ float red[256];
    __shared__ int   list[NBLK];
    __shared__ int   cnt;

    if (tid == 0) cnt = 0;
    float m = (tid < NBLK) ? g_blockmax[(b * NBLK + tid) * NG + g] : 0.0f;
    red[tid] = m;
    __syncthreads();
#pragma unroll
    for (int s = 128; s; s >>= 1) {
        if (tid < s) red[tid] = fmaxf(red[tid], red[tid + s]);
        __syncthreads();
    }
    const float shigh = red[0];

    if (tid < NBLK && m == shigh) {
        int i = atomicAdd(&cnt, 1);
        list[i] = tid;
    }
    __syncthreads();

    const int n = cnt;
    float4 gb = gts[b * NG + g];
    float  ag = box_area(gb);

    for (int i = 0; i < n; ++i) {
        int blk = list[i];
#pragma unroll
        for (int k = 0; k < 6; ++k) {       // covers both the 6- and 5-anchor blocks
            int a = blk * 256 + k * K1_STRIDE + tid;
            if (a < NA) {
                float4 an = anchors[b * NA + a];
                float v = iou_pair(an, box_area(an), gb, ag);
                if (v == shigh) g_lowq[b * NA + a] = 1;
            }
        }
    }
}

// ---------------------------------------------------------------------------
// K3: label + matched-box writer.
// ---------------------------------------------------------------------------
__global__ __launch_bounds__(256)
void k_label(const float4* __restrict__ gts, const float* __restrict__ scores,
             const int* __restrict__ confs,
             float* __restrict__ outL, float4* __restrict__ outB)
{
    const int b = blockIdx.y;
    const int tid = threadIdx.x;

    __shared__ float4 sg[NG];
    __shared__ float  ss[NG];
    __shared__ int    sc[NG];
    if (tid < NG) {
        sg[tid] = gts[b * NG + tid];
        ss[tid] = scores[b * NG + tid];
        sc[tid] = confs[b * NG + tid];
    }
    __syncthreads();

    const int a = blockIdx.x * 256 + tid;   // NA = 625*256 exactly
    const int idx = b * NA + a;

    uint2 bb = g_best[idx];
    float best = __uint_as_float(bb.x);
    int bestg = (int)bb.y;
    bool lowq = g_lowq[idx] != 0;

    // Matcher: <0.3 -> -1 ; <0.7 -> -2 ; else match. Low-quality override.
    int midx = lowq ? bestg
                    : (best >= 0.7f ? bestg : (best >= 0.3f ? -2 : -1));
    int cl = midx >= 0 ? midx : 0;

    float s = ss[cl];
    int c = sc[cl];
    float label = (midx == -1) ? 0.0f
                : (midx == -2) ? -1.0f
                : ((s < 1.0f || c == 0) ? -1.0f : 1.0f);

    outL[idx] = label;
    outB[idx] = sg[cl];
}

extern "C" void kernel_launch(void* const* d_in, const int* in_sizes, int n_in,
                              void* d_out, int out_size) {
    (void)in_sizes; (void)n_in; (void)out_size;
    const float4* anchors = (const float4*)d_in[0];   // [B, A, 4] f32
    const float4* gts     = (const float4*)d_in[1];   // [B, G, 4] f32
    const float*  scores  = (const float*)d_in[2];    // [B, G] f32
    const int*    confs   = (const int*)d_in[3];      // [B, G] i32

    float*  outL = (float*)d_out;                      // labels [B, A]
    float4* outB = (float4*)((float*)d_out + NB * NA); // matched boxes [B, A, 4]

    k_main <<<dim3(NBLK, NB), 256>>>(anchors, gts);
    k_lowq <<<dim3(NG,   NB), 256>>>(anchors, gts);
    k_label<<<dim3(NA / 256, NB), 256>>>(gts, scores, confs, outL, outB);
}

// round 9
// speedup vs baseline: 1.0950x; 1.0950x over previous
#include <cuda_runtime.h>

#define NB 4
#define NA 160000
#define NG 64
#define NBLK 74              // K1 blocks per batch image (grid 74*4 = 296 = 2*148: one wave @occ2)
#define K1_STRIDE (NBLK*256) // 18944
#define NBLK9 33             // blocks 0..32: 9 anchors/thread; 33..73: 8  (33*9+41*8=625)

// Scratch (__device__ globals; no init required by construction)
// g_best.y layout: bits[0:6] = argmax gt, bit 31 = low-quality flag (set by K2).
__device__ uint2 g_best[NB * NA];
__device__ float g_blockmax[NB * NBLK * NG]; // per-block per-gt rounded col max

// Same _rn sequence everywhere + __fdividef everywhere => any (anchor,gt) IoU
// is bit-identical between K1 and K2, so K2's rounded-equality rescan matches
// the reference's  mq == highest_per_gt  exactly.
__device__ __forceinline__ float box_area(float4 b) {
    return __fmul_rn(__fadd_rn(b.z, -b.x), __fadd_rn(b.w, -b.y));
}

__device__ __forceinline__ float iou_pair(float4 a, float areaA, float4 g, float areaG) {
    float ltx = fmaxf(g.x, a.x);
    float lty = fmaxf(g.y, a.y);
    float rbx = fminf(g.z, a.z);
    float rby = fminf(g.w, a.w);
    float w = fmaxf(__fadd_rn(rbx, -ltx), 0.0f);
    float h = fmaxf(__fadd_rn(rby, -lty), 0.0f);
    float inter = __fmul_rn(w, h);
    float denom = __fadd_rn(__fadd_rn(areaA, areaG), -inter);
    return __fdividef(inter, denom);   // RCP+FMUL; inter==0 -> exactly 0; denom>0 always
}

__device__ __forceinline__ unsigned warp_max_u32(unsigned v) {
    unsigned r;
    asm("redux.sync.max.u32 %0, %1, 0xffffffff;" : "=r"(r) : "r"(v));
    return r;
}

// ---------------------------------------------------------------------------
// K1: single full IoU pass on direct rounded quotients (reference semantics).
// Per thread: KA anchors in registers. Produces per-anchor (best, bestg) and
// per-block per-gt rounded column max.
// ---------------------------------------------------------------------------
template <int KA>
__device__ __forceinline__ void k1_body(
    const float4* __restrict__ anchors, int b, int blk, int tid,
    const float4* sg, const float* sga, unsigned int* smax)
{
    const int a0 = blk * 256 + tid;
    const int lane = tid & 31;

    float4 an[KA]; float areaA[KA]; float best[KA]; int bg[KA];
#pragma unroll
    for (int k = 0; k < KA; ++k) {
        int a = a0 + k * K1_STRIDE;
        an[k] = anchors[b * NA + a];
        areaA[k] = box_area(an[k]);
        best[k] = -1.0f;               // first g always wins -> first-occurrence argmax
        bg[k] = 0;
    }

    float gown[2] = {0.0f, 0.0f};      // rounded tile col-max for g = lane, lane+32

#pragma unroll 2
    for (int g = 0; g < NG; ++g) {
        float4 gb = sg[g];
        float  ag = sga[g];

        float cmax = 0.0f;             // this thread's column-max candidate
#pragma unroll
        for (int k = 0; k < KA; ++k) {
            float q = iou_pair(an[k], areaA[k], gb, ag);
            cmax = fmaxf(cmax, q);
            if (q > best[k]) { best[k] = q; bg[k] = g; }   // strict >: first occurrence
        }

        // single-instruction warp max (IoU >= 0: uint order == float order)
        unsigned wm = warp_max_u32(__float_as_uint(cmax));
        if (lane == (g & 31))
            gown[g >> 5] = __uint_as_float(wm);
    }

#pragma unroll
    for (int k = 0; k < KA; ++k) {
        int a = a0 + k * K1_STRIDE;
        g_best[b * NA + a] = make_uint2(__float_as_uint(best[k]), (unsigned)bg[k]);
    }

    // block-level rounded col-max
    atomicMax(&smax[lane],      __float_as_uint(gown[0]));
    atomicMax(&smax[lane + 32], __float_as_uint(gown[1]));
}

__global__ __launch_bounds__(256, 2)
void k_main(const float4* __restrict__ anchors, const float4* __restrict__ gts)
{
    const int b = blockIdx.y;
    const int blk = blockIdx.x;
    const int tid = threadIdx.x;

    __shared__ float4 sg[NG];
    __shared__ float  sga[NG];
    __shared__ unsigned int smax[NG];

    if (tid < NG) {
        float4 g = gts[b * NG + tid];
        sg[tid] = g;
        sga[tid] = box_area(g);
        smax[tid] = 0u;
    }
    __syncthreads();

    if (blk < NBLK9) k1_body<9>(anchors, b, blk, tid, sg, sga, smax);
    else             k1_body<8>(anchors, b, blk, tid, sg, sga, smax);

    __syncthreads();
    if (tid < NG)
        g_blockmax[(b * NBLK + blk) * NG + tid] = __uint_as_float(smax[tid]);
}

// ---------------------------------------------------------------------------
// K2: sparse low-quality pass. One block per (gt,batch) column: reduce the 74
// block maxima to the global column max, rescan only blocks achieving it, set
// bit 31 of g_best.y for anchors whose rounded IoU equals it (exact reference
// semantics; writes are sparse so atomicOr cost is negligible).
// ---------------------------------------------------------------------------
__global__ __launch_bounds__(256)
void k_lowq(const float4* __restrict__ anchors, const float4* __restrict__ gts)
{
    const int g = blockIdx.x;
    const int b = blockIdx.y;
    const int tid = threadIdx.x;

    __shared__ float red[256];
    __shared__ int   list[NBLK];
    __shared__ int   cnt;

    if (tid == 0) cnt = 0;
    float m = (tid < NBLK) ? g_blockmax[(b * NBLK + tid) * NG + g] : 0.0f;
    red[tid] = m;
    __syncthreads();
#pragma unroll
    for (int s = 128; s; s >>= 1) {
        if (tid < s) red[tid] = fmaxf(red[tid], red[tid + s]);
        __syncthreads();
    }
    const float shigh = red[0];

    if (tid < NBLK && m == shigh) {
        int i = atomicAdd(&cnt, 1);
        list[i] = tid;
    }
    __syncthreads();

    const int n = cnt;
    float4 gb = gts[b * NG + g];
    float  ag = box_area(gb);

    for (int i = 0; i < n; ++i) {
        int blk = list[i];
#pragma unroll
        for (int k = 0; k < 9; ++k) {       // covers both the 9- and 8-anchor blocks
            int a = blk * 256 + k * K1_STRIDE + tid;
            if (a < NA) {
                float4 an = anchors[b * NA + a];
                float v = iou_pair(an, box_area(an), gb, ag);
                if (v == shigh)
                    atomicOr(&g_best[b * NA + a].y, 0x80000000u);
            }
        }
    }
}

// ---------------------------------------------------------------------------
// K3: label + matched-box writer.
// ---------------------------------------------------------------------------
__global__ __launch_bounds__(256)
void k_label(const float4* __restrict__ gts, const float* __restrict__ scores,
             const int* __restrict__ confs,
             float* __restrict__ outL, float4* __restrict__ outB)
{
    const int b = blockIdx.y;
    const int tid = threadIdx.x;

    __shared__ float4 sg[NG];
    __shared__ float  ss[NG];
    __shared__ int    sc[NG];
    if (tid < NG) {
        sg[tid] = gts[b * NG + tid];
        ss[tid] = scores[b * NG + tid];
        sc[tid] = confs[b * NG + tid];
    }
    __syncthreads();

    const int a = blockIdx.x * 256 + tid;   // NA = 625*256 exactly
    const int idx = b * NA + a;

    uint2 bb = g_best[idx];
    float best = __uint_as_float(bb.x);
    int bestg = (int)(bb.y & 0x3Fu);
    bool lowq = (bb.y & 0x80000000u) != 0u;

    // Matcher: <0.3 -> -1 ; <0.7 -> -2 ; else match. Low-quality override.
    int midx = lowq ? bestg
                    : (best >= 0.7f ? bestg : (best >= 0.3f ? -2 : -1));
    int cl = midx >= 0 ? midx : 0;

    float s = ss[cl];
    int c = sc[cl];
    float label = (midx == -1) ? 0.0f
                : (midx == -2) ? -1.0f
                : ((s < 1.0f || c == 0) ? -1.0f : 1.0f);

    outL[idx] = label;
    outB[idx] = sg[cl];
}

extern "C" void kernel_launch(void* const* d_in, const int* in_sizes, int n_in,
                              void* d_out, int out_size) {
    (void)in_sizes; (void)n_in; (void)out_size;
    const float4* anchors = (const float4*)d_in[0];   // [B, A, 4] f32
    const float4* gts     = (const float4*)d_in[1];   // [B, G, 4] f32
    const float*  scores  = (const float*)d_in[2];    // [B, G] f32
    const int*    confs   = (const int*)d_in[3];      // [B, G] i32

    float*  outL = (float*)d_out;                      // labels [B, A]
    float4* outB = (float4*)((float*)d_out + NB * NA); // matched boxes [B, A, 4]

    k_main <<<dim3(NBLK, NB), 256>>>(anchors, gts);
    k_lowq <<<dim3(NG,   NB), 256>>>(anchors, gts);
    k_label<<<dim3(NA / 256, NB), 256>>>(gts, scores, confs, outL, outB);
}

// round 10
// speedup vs baseline: 1.1012x; 1.0056x over previous
#include <cuda_runtime.h>

#define NB 4
#define NA 160000
#define NG 64
#define NBLK 74              // K1 blocks per batch image (grid 74*4 = 296 = 2*148: one wave @occ2)
#define K1_STRIDE (NBLK*256) // 18944
#define NBLK9 33             // blocks 0..32: 9 anchors/thread; 33..73: 8  (33*9+41*8=625)

// Scratch (__device__ globals; no init required by construction)
// g_best[i]: bits[0:31) = float bits of best (rounded) IoU; bit 31 = lowq flag (K2).
__device__ unsigned g_best[NB * NA];
__device__ float    g_blockmax[NB * NBLK * NG]; // per-block per-gt rounded col max

// Same _rn sequence everywhere + __fdividef everywhere => any (anchor,gt) IoU
// is bit-identical across K1 / K2 / K3's sparse argmax recompute. That makes
// K2's rounded-equality rescan and K3's "first g with q == best" exactly the
// reference's  mq == highest_per_gt  and  jnp.argmax  semantics.
__device__ __forceinline__ float box_area(float4 b) {
    return __fmul_rn(__fadd_rn(b.z, -b.x), __fadd_rn(b.w, -b.y));
}

__device__ __forceinline__ float iou_pair(float4 a, float areaA, float4 g, float areaG) {
    float ltx = fmaxf(g.x, a.x);
    float lty = fmaxf(g.y, a.y);
    float rbx = fminf(g.z, a.z);
    float rby = fminf(g.w, a.w);
    float w = fmaxf(__fadd_rn(rbx, -ltx), 0.0f);
    float h = fmaxf(__fadd_rn(rby, -lty), 0.0f);
    float inter = __fmul_rn(w, h);
    float denom = __fadd_rn(__fadd_rn(areaA, areaG), -inter);
    return __fdividef(inter, denom);   // inter==0 -> exactly 0; denom>0 always
}

__device__ __forceinline__ unsigned warp_max_u32(unsigned v) {
    unsigned r;
    asm("redux.sync.max.u32 %0, %1, 0xffffffff;" : "=r"(r) : "r"(v));
    return r;
}

// ---------------------------------------------------------------------------
// K1: single full IoU pass; per pair only two fmax trackers (NO argmax here —
// bestg is recovered sparsely in K3 for the rare positive anchors).
// ---------------------------------------------------------------------------
template <int KA>
__device__ __forceinline__ void k1_body(
    const float4* __restrict__ anchors, int b, int blk, int tid,
    const float4* sg, const float* sga, unsigned int* smax)
{
    const int a0 = blk * 256 + tid;
    const int lane = tid & 31;

    float4 an[KA]; float areaA[KA]; float best[KA];
#pragma unroll
    for (int k = 0; k < KA; ++k) {
        int a = a0 + k * K1_STRIDE;
        an[k] = anchors[b * NA + a];
        areaA[k] = box_area(an[k]);
        best[k] = 0.0f;                // q >= 0, so fmax chain == true max
    }

    float gown[2] = {0.0f, 0.0f};      // rounded tile col-max for g = lane, lane+32

#pragma unroll 2
    for (int g = 0; g < NG; ++g) {
        float4 gb = sg[g];
        float  ag = sga[g];

        float cmax = 0.0f;
#pragma unroll
        for (int k = 0; k < KA; ++k) {
            float q = iou_pair(an[k], areaA[k], gb, ag);
            cmax = fmaxf(cmax, q);
            best[k] = fmaxf(best[k], q);
        }

        unsigned wm = warp_max_u32(__float_as_uint(cmax));
        if (lane == (g & 31))
            gown[g >> 5] = __uint_as_float(wm);
    }

#pragma unroll
    for (int k = 0; k < KA; ++k) {
        int a = a0 + k * K1_STRIDE;
        g_best[b * NA + a] = __float_as_uint(best[k]);   // bit31 clear (best >= 0)
    }

    atomicMax(&smax[lane],      __float_as_uint(gown[0]));
    atomicMax(&smax[lane + 32], __float_as_uint(gown[1]));
}

__global__ __launch_bounds__(256, 2)
void k_main(const float4* __restrict__ anchors, const float4* __restrict__ gts)
{
    const int b = blockIdx.y;
    const int blk = blockIdx.x;
    const int tid = threadIdx.x;

    __shared__ float4 sg[NG];
    __shared__ float  sga[NG];
    __shared__ unsigned int smax[NG];

    if (tid < NG) {
        float4 g = gts[b * NG + tid];
        sg[tid] = g;
        sga[tid] = box_area(g);
        smax[tid] = 0u;
    }
    __syncthreads();

    if (blk < NBLK9) k1_body<9>(anchors, b, blk, tid, sg, sga, smax);
    else             k1_body<8>(anchors, b, blk, tid, sg, sga, smax);

    __syncthreads();
    if (tid < NG)
        g_blockmax[(b * NBLK + blk) * NG + tid] = __uint_as_float(smax[tid]);
}

// ---------------------------------------------------------------------------
// K2: sparse low-quality pass. One block per (gt,batch) column: reduce the 74
// block maxima to the column max, rescan only blocks achieving it, set bit 31
// of g_best for anchors whose rounded IoU equals it.
// ---------------------------------------------------------------------------
__global__ __launch_bounds__(256)
void k_lowq(const float4* __restrict__ anchors, const float4* __restrict__ gts)
{
    const int g = blockIdx.x;
    const int b = blockIdx.y;
    const int tid = threadIdx.x;

    __shared__ float red[256];
    __shared__ int   list[NBLK];
    __shared__ int   cnt;

    if (tid == 0) cnt = 0;
    float m = (tid < NBLK) ? g_blockmax[(b * NBLK + tid) * NG + g] : 0.0f;
    red[tid] = m;
    __syncthreads();
#pragma unroll
    for (int s = 128; s; s >>= 1) {
        if (tid < s) red[tid] = fmaxf(red[tid], red[tid + s]);
        __syncthreads();
    }
    const float shigh = red[0];

    if (tid < NBLK && m == shigh) {
        int i = atomicAdd(&cnt, 1);
        list[i] = tid;
    }
    __syncthreads();

    const int n = cnt;
    float4 gb = gts[b * NG + g];
    float  ag = box_area(gb);

    for (int i = 0; i < n; ++i) {
        int blk = list[i];
#pragma unroll
        for (int k = 0; k < 9; ++k) {       // covers both the 9- and 8-anchor blocks
            int a = blk * 256 + k * K1_STRIDE + tid;
            if (a < NA) {
                float4 an = anchors[b * NA + a];
                float v = iou_pair(an, box_area(an), gb, ag);
                if (v == shigh)
                    atomicOr(&g_best[b * NA + a], 0x80000000u);
            }
        }
    }
}

// ---------------------------------------------------------------------------
// K3: label + matched-box writer, with SPARSE argmax recovery: only positive
// anchors (lowq or best >= 0.7) re-scan the 64 GTs for the first g whose
// bit-identical IoU equals best (== reference first-occurrence argmax).
// ---------------------------------------------------------------------------
__global__ __launch_bounds__(256)
void k_label(const float4* __restrict__ gts, const float* __restrict__ scores,
             const int* __restrict__ confs,
             float* __restrict__ outL, float4* __restrict__ outB)
{
    const int b = blockIdx.y;
    const int tid = threadIdx.x;

    __shared__ float4 sg[NG];
    __shared__ float  sga[NG];
    __shared__ float  ss[NG];
    __shared__ int    sc[NG];
    if (tid < NG) {
        float4 g = gts[b * NG + tid];
        sg[tid] = g;
        sga[tid] = box_area(g);
        ss[tid] = scores[b * NG + tid];
        sc[tid] = confs[b * NG + tid];
    }
    __syncthreads();

    const int a = blockIdx.x * 256 + tid;   // NA = 625*256 exactly
    const int idx = b * NA + a;

    const float4* __restrict__ anchors = outB ? nullptr : nullptr; // (unused)

    unsigned bb = g_best[idx];
    bool lowq = (bb & 0x80000000u) != 0u;
    float best = __uint_as_float(bb & 0x7FFFFFFFu);
    bool pos = lowq || (best >= 0.7f);

    int bestg = 0;
    if (pos) {
        // recompute this anchor's IoUs; first g with q == best is the argmax
        float4 an = ((const float4*)0) == 0 ? make_float4(0,0,0,0) : make_float4(0,0,0,0);
        (void)an;
        // anchor reload happens via the extra parameter below
    }

    // NOTE: anchor needed only for positive lanes; loaded unconditionally is
    // cheap (one coalesced float4 per thread).
    // (actual load + recompute done in k_label2 path below)
    outL[idx] = 0.0f; // placeholder overwritten below
    (void)bestg; (void)best; (void)pos; (void)lowq;
    // -- this kernel variant replaced by k_label_full below --
}

// Full K3 (used): includes anchor pointer for sparse argmax recovery.
__global__ __launch_bounds__(256)
void k_label_full(const float4* __restrict__ anchors,
                  const float4* __restrict__ gts, const float* __restrict__ scores,
                  const int* __restrict__ confs,
                  float* __restrict__ outL, float4* __restrict__ outB)
{
    const int b = blockIdx.y;
    const int tid = threadIdx.x;

    __shared__ float4 sg[NG];
    __shared__ float  sga[NG];
    __shared__ float  ss[NG];
    __shared__ int    sc[NG];
    if (tid < NG) {
        float4 g = gts[b * NG + tid];
        sg[tid] = g;
        sga[tid] = box_area(g);
        ss[tid] = scores[b * NG + tid];
        sc[tid] = confs[b * NG + tid];
    }
    __syncthreads();

    const int a = blockIdx.x * 256 + tid;   // NA = 625*256 exactly
    const int idx = b * NA + a;

    unsigned bb = g_best[idx];
    bool lowq = (bb & 0x80000000u) != 0u;
    float best = __uint_as_float(bb & 0x7FFFFFFFu);
    bool pos = lowq || (best >= 0.7f);

    int bestg = 0;
    if (pos) {
        float4 an = anchors[idx];
        float areaA = box_area(an);
#pragma unroll 4
        for (int g = 0; g < NG; ++g) {
            if (iou_pair(an, areaA, sg[g], sga[g]) == best) { bestg = g; break; }
        }
    }

    // Matcher: positive -> bestg ; else <0.3 -> -1 ; else (0.3..0.7) -> -2.
    int midx = pos ? bestg : (best >= 0.3f ? -2 : -1);
    int cl = pos ? bestg : 0;

    float s = ss[cl];
    int c = sc[cl];
    float label = (midx == -1) ? 0.0f
                : (midx == -2) ? -1.0f
                : ((s < 1.0f || c == 0) ? -1.0f : 1.0f);

    outL[idx] = label;
    outB[idx] = sg[cl];
}

extern "C" void kernel_launch(void* const* d_in, const int* in_sizes, int n_in,
                              void* d_out, int out_size) {
    (void)in_sizes; (void)n_in; (void)out_size;
    const float4* anchors = (const float4*)d_in[0];   // [B, A, 4] f32
    const float4* gts     = (const float4*)d_in[1];   // [B, G, 4] f32
    const float*  scores  = (const float*)d_in[2];    // [B, G] f32
    const int*    confs   = (const int*)d_in[3];      // [B, G] i32

    float*  outL = (float*)d_out;                      // labels [B, A]
    float4* outB = (float4*)((float*)d_out + NB * NA); // matched boxes [B, A, 4]

    k_main      <<<dim3(NBLK, NB), 256>>>(anchors, gts);
    k_lowq      <<<dim3(NG,   NB), 256>>>(anchors, gts);
    k_label_full<<<dim3(NA / 256, NB), 256>>>(anchors, gts, scores, confs, outL, outB);
}